// round 4
// baseline (speedup 1.0000x reference)
#include <cuda_runtime.h>
#include <math.h>
#include <stdint.h>

// ---------------- static device scratch (no allocation allowed) ----------------
__device__ float    g_xg1 [(size_t)32768 * 1024];   // layer1 input projection, layout [b][t][j*4+g]
__device__ float    g_out1[(size_t)32768 * 256];    // layer1 hidden outputs [b][t][j] (tf32-rounded)
__device__ float    g_xg2 [(size_t)32768 * 512];    // layer2 input projection [b][t][j*4+g]
__device__ float    g_w1cv[(size_t)1024 * 2048];    // Wih1 rounded to tf32
__device__ float    g_w2cv[(size_t)512 * 256];      // Wih2 rounded to tf32
__device__ float    g_h1  [2 * 64 * 256];           // double-buffered h, layer1
__device__ float    g_h2  [2 * 64 * 128];           // double-buffered h, layer2
__device__ unsigned g_bar1;
__device__ unsigned g_bar2;

// ---------------- helpers ----------------
__device__ __forceinline__ unsigned f2tf32(float f) {
    unsigned r;
    asm("cvt.rna.tf32.f32 %0, %1;" : "=r"(r) : "f"(f));
    return r;
}

__device__ __forceinline__ void mma_tf32(float* c, const unsigned* a, const unsigned* b) {
    asm volatile(
        "mma.sync.aligned.m16n8k8.row.col.f32.tf32.tf32.f32 "
        "{%0,%1,%2,%3},{%4,%5,%6,%7},{%8,%9},{%0,%1,%2,%3};"
        : "+f"(c[0]), "+f"(c[1]), "+f"(c[2]), "+f"(c[3])
        : "r"(a[0]), "r"(a[1]), "r"(a[2]), "r"(a[3]), "r"(b[0]), "r"(b[1]));
}

__device__ __forceinline__ void cp_async16(void* smem_dst, const void* gptr) {
    unsigned s = (unsigned)__cvta_generic_to_shared(smem_dst);
    asm volatile("cp.async.cg.shared.global [%0], [%1], 16;\n" :: "r"(s), "l"(gptr));
}
#define CP_COMMIT() asm volatile("cp.async.commit_group;\n" ::: "memory")
#define CP_WAIT0()  asm volatile("cp.async.wait_group 0;\n" ::: "memory")

__device__ __forceinline__ void red_release_gpu_add(unsigned* p) {
    asm volatile("red.release.gpu.global.add.u32 [%0], 1;" :: "l"(p) : "memory");
}
__device__ __forceinline__ unsigned ld_acquire_gpu(const unsigned* p) {
    unsigned v;
    asm volatile("ld.acquire.gpu.global.u32 %0, [%1];" : "=r"(v) : "l"(p) : "memory");
    return v;
}

// ---------------- prep: round weights to tf32 once ----------------
__global__ void cvt_rna_kernel(const float* __restrict__ src, float* __restrict__ dst, int n) {
    int i = blockIdx.x * 256 + threadIdx.x;
    if (i < n) dst[i] = __uint_as_float(f2tf32(src[i]));
}

// ---------------- tf32 GEMM with permuted output columns ----------------
// C[m][n'] = sum_k A[m][k] * W[srcrow(n')][k] + bias(srcrow(n'))
// n' = j*4+g maps to source row g*H + j (H = N/4). Biases b1+b2 added.
// Tiles: 128M x 128N x 32K, 256 threads, double-buffered cp.async.
__global__ void __launch_bounds__(256, 2) gemm_tf32_perm(
    const float* __restrict__ A, const float* __restrict__ W,
    const float* __restrict__ b1, const float* __restrict__ b2,
    float* __restrict__ C, int M, int N, int K)
{
    extern __shared__ unsigned sh[];
    unsigned* As = sh;                 // [2][128][36]
    unsigned* Bs = sh + 2 * 128 * 36;  // [2][128][36]

    const int tid = threadIdx.x, lane = tid & 31, warp = tid >> 5;
    const int wm = warp & 1, wn = warp >> 1;   // 2 x 4 warp grid, warp tile 64x32
    const int g = lane >> 2, tg = lane & 3;
    const int bn = blockIdx.x * 128, bm = blockIdx.y * 128;
    const int H = N >> 2;

    float acc[4][4][4];
#pragma unroll
    for (int a = 0; a < 4; a++)
#pragma unroll
        for (int b = 0; b < 4; b++)
#pragma unroll
            for (int c = 0; c < 4; c++) acc[a][b][c] = 0.f;

    const int NK = K >> 5;

    // prologue: tile 0
#pragma unroll
    for (int i = 0; i < 4; i++) {
        int id = tid + i * 256, row = id >> 3, c4 = id & 7;
        cp_async16(&As[row * 36 + c4 * 4], A + (size_t)(bm + row) * K + c4 * 4);
        int np = bn + row;
        int srow = (np & 3) * H + (np >> 2);
        cp_async16(&Bs[row * 36 + c4 * 4], W + (size_t)srow * K + c4 * 4);
    }
    CP_COMMIT();

    int buf = 0;
    for (int kt = 0; kt < NK; kt++) {
        CP_WAIT0();
        __syncthreads();
        if (kt + 1 < NK) {
            int koff = (kt + 1) * 32;
            int nb = buf ^ 1;
#pragma unroll
            for (int i = 0; i < 4; i++) {
                int id = tid + i * 256, row = id >> 3, c4 = id & 7;
                cp_async16(&As[nb * 128 * 36 + row * 36 + c4 * 4],
                           A + (size_t)(bm + row) * K + koff + c4 * 4);
                int np = bn + row;
                int srow = (np & 3) * H + (np >> 2);
                cp_async16(&Bs[nb * 128 * 36 + row * 36 + c4 * 4],
                           W + (size_t)srow * K + koff + c4 * 4);
            }
        }
        CP_COMMIT();

        const unsigned* Ab = As + buf * 128 * 36;
        const unsigned* Bb = Bs + buf * 128 * 36;
#pragma unroll
        for (int ks = 0; ks < 4; ks++) {
            unsigned af[4][4], bf[4][2];
#pragma unroll
            for (int mt = 0; mt < 4; mt++) {
                int r = wm * 64 + mt * 16 + g;
                af[mt][0] = Ab[r * 36 + ks * 8 + tg];
                af[mt][1] = Ab[(r + 8) * 36 + ks * 8 + tg];
                af[mt][2] = Ab[r * 36 + ks * 8 + tg + 4];
                af[mt][3] = Ab[(r + 8) * 36 + ks * 8 + tg + 4];
            }
#pragma unroll
            for (int nt = 0; nt < 4; nt++) {
                int nl = wn * 32 + nt * 8 + g;
                bf[nt][0] = Bb[nl * 36 + ks * 8 + tg];
                bf[nt][1] = Bb[nl * 36 + ks * 8 + tg + 4];
            }
#pragma unroll
            for (int mt = 0; mt < 4; mt++)
#pragma unroll
                for (int nt = 0; nt < 4; nt++)
                    mma_tf32(acc[mt][nt], af[mt], bf[nt]);
        }
        buf ^= 1;
    }

    // epilogue: permuted bias + store
#pragma unroll
    for (int mt = 0; mt < 4; mt++) {
        int r0 = bm + wm * 64 + mt * 16 + g;
#pragma unroll
        for (int nt = 0; nt < 4; nt++) {
            int c = bn + wn * 32 + nt * 8 + tg * 2;
            int s0 = (c & 3) * H + (c >> 2);
            int s1 = ((c + 1) & 3) * H + ((c + 1) >> 2);
            float bb0 = b1[s0] + b2[s0];
            float bb1 = b1[s1] + b2[s1];
            C[(size_t)r0 * N + c]           = acc[mt][nt][0] + bb0;
            C[(size_t)r0 * N + c + 1]       = acc[mt][nt][1] + bb1;
            C[(size_t)(r0 + 8) * N + c]     = acc[mt][nt][2] + bb0;
            C[(size_t)(r0 + 8) * N + c + 1] = acc[mt][nt][3] + bb1;
        }
    }
}

// ---------------- persistent LSTM recurrence on tensor cores, v3 ----------------
// NBLK blocks x 256 threads; block owns 8 hidden cols = 32 gate rows
// (col c = jl*4+gg -> source gate row gg*HD + jbase + jl).
// Per step: C[64][32] = h[64][HD] * w[32][HD]^T, warps: wm (m-half, 32 batches)
// x wkh (k-quarter). Partials in SMEM [4][64][36]; all 256 threads update
// 2 hidden units each. Grid sync: syncthreads + red.release / ld.acquire poll.
template <int HD, int NBLK, bool STORE_OUT>
__global__ void __launch_bounds__(256, 1) lstm_recur_v3(
    const float* __restrict__ xg,    // [b][t][j*4+g]
    const float* __restrict__ Whh,   // [4*HD][HD]
    float* h_glob,                   // [2][64][HD]
    float* out,                      // [b][t][HD] or unused
    unsigned* bar, int T)
{
    constexpr int HP = HD + 4;       // padded uint stride
    constexpr int KQ = HD / 4;       // k per warp (k-quarter)
    constexpr int NKS = KQ / 8;      // mma k-steps per warp
    constexpr int C4 = HD / 4;       // float4 per h row

    extern __shared__ unsigned smem_u[];
    unsigned* hs = smem_u;                     // [64][HP] tf32 h
    unsigned* ws = hs + 64 * HP;               // [32][HP] tf32 weights
    float* part  = (float*)(ws + 32 * HP);     // [4][64][36]

    const int tid = threadIdx.x, lane = tid & 31, warp = tid >> 5;
    const int wm = warp & 1, wkh = warp >> 1;
    const int g = lane >> 2, tg = lane & 3;
    const int jbase = blockIdx.x * 8;

    // load + round this block's 32 weight rows (col c -> src row (c&3)*HD + jbase + (c>>2))
    for (int i = tid; i < 32 * HD; i += 256) {
        int c = i / HD, k = i & (HD - 1);
        int srow = (c & 3) * HD + jbase + (c >> 2);
        ws[c * HP + k] = f2tf32(Whh[(size_t)srow * HD + k]);
    }

    // updater mapping: thread handles units u = tid and u+256; u -> (b=u>>3, jl=u&7)
    const int b0  = tid >> 3,        jl0 = tid & 7;
    const int b1_ = (tid + 256) >> 3, jl1 = tid & 7;   // (tid+256)&7 == tid&7
    const float* xp0 = xg + ((size_t)b0  * T) * (4 * HD) + (jbase + jl0) * 4;
    const float* xp1 = xg + ((size_t)b1_ * T) * (4 * HD) + (jbase + jl1) * 4;
    float cc0 = 0.f, cc1 = 0.f;

    for (int t = 0; t < T; t++) {
        const float* hread = h_glob + (size_t)(t & 1) * 64 * HD;
        float*       hwrit = h_glob + (size_t)((t + 1) & 1) * 64 * HD;

        // prefetch this step's xg (independent of h)
        float4 xv0 = *(const float4*)(xp0 + (size_t)t * (4 * HD));
        float4 xv1 = *(const float4*)(xp1 + (size_t)t * (4 * HD));

        // stage previous h (all batches) into SMEM as tf32
        const float4* hr4 = (const float4*)hread;
        for (int i = tid; i < 64 * C4; i += 256) {
            int bb = i / C4, k4 = i & (C4 - 1);
            float4 v = __ldcg(hr4 + i);
            uint4 u = make_uint4(f2tf32(v.x), f2tf32(v.y), f2tf32(v.z), f2tf32(v.w));
            *(uint4*)(hs + bb * HP + k4 * 4) = u;
        }
        __syncthreads();

        // mma: C[64][32], this warp: rows wm*32..+32, k-range wkh*KQ..+KQ
        float acc[2][4][4];
#pragma unroll
        for (int a = 0; a < 2; a++)
#pragma unroll
            for (int bq = 0; bq < 4; bq++)
#pragma unroll
                for (int cq = 0; cq < 4; cq++) acc[a][bq][cq] = 0.f;

        const unsigned* ha = hs + (wm * 32 + g) * HP + wkh * KQ;
        const unsigned* wb = ws + g * HP + wkh * KQ;
#pragma unroll
        for (int ks = 0; ks < NKS; ks++) {
            unsigned af[2][4], bf[4][2];
            int co = ks * 8 + tg;
#pragma unroll
            for (int mt = 0; mt < 2; mt++) {
                const unsigned* hm = ha + mt * 16 * HP;
                af[mt][0] = hm[co];
                af[mt][1] = hm[8 * HP + co];
                af[mt][2] = hm[co + 4];
                af[mt][3] = hm[8 * HP + co + 4];
            }
#pragma unroll
            for (int nt = 0; nt < 4; nt++) {
                bf[nt][0] = wb[nt * 8 * HP + co];
                bf[nt][1] = wb[nt * 8 * HP + co + 4];
            }
#pragma unroll
            for (int mt = 0; mt < 2; mt++)
#pragma unroll
                for (int nt = 0; nt < 4; nt++)
                    mma_tf32(acc[mt][nt], af[mt], bf[nt]);
        }

        // write partials: part[(wkh*64 + row)*36 + col]
#pragma unroll
        for (int mt = 0; mt < 2; mt++) {
            int row = wm * 32 + mt * 16 + g;
#pragma unroll
            for (int nt = 0; nt < 4; nt++) {
                int col = nt * 8 + tg * 2;
                float2* p0 = (float2*)(part + (wkh * 64 + row) * 36 + col);
                float2* p1 = (float2*)(part + (wkh * 64 + row + 8) * 36 + col);
                *p0 = make_float2(acc[mt][nt][0], acc[mt][nt][1]);
                *p1 = make_float2(acc[mt][nt][2], acc[mt][nt][3]);
            }
        }
        __syncthreads();

        // update: 2 hidden units per thread
        {
            // unit 0
            float4 p0 = *(const float4*)(part + (0 * 64 + b0) * 36 + jl0 * 4);
            float4 p1 = *(const float4*)(part + (1 * 64 + b0) * 36 + jl0 * 4);
            float4 p2 = *(const float4*)(part + (2 * 64 + b0) * 36 + jl0 * 4);
            float4 p3 = *(const float4*)(part + (3 * 64 + b0) * 36 + jl0 * 4);
            float gi = xv0.x + ((p0.x + p1.x) + (p2.x + p3.x));
            float gf = xv0.y + ((p0.y + p1.y) + (p2.y + p3.y));
            float gc = xv0.z + ((p0.z + p1.z) + (p2.z + p3.z));
            float go = xv0.w + ((p0.w + p1.w) + (p2.w + p3.w));
            float iv = 1.f / (1.f + __expf(-gi));
            float fv = 1.f / (1.f + __expf(-gf));
            float gv = tanhf(gc);
            float ov = 1.f / (1.f + __expf(-go));
            cc0 = fv * cc0 + iv * gv;
            float h = ov * tanhf(cc0);
            float hr = __uint_as_float(f2tf32(h));
            __stcg(hwrit + b0 * HD + jbase + jl0, hr);
            if (STORE_OUT) out[((size_t)b0 * T + t) * HD + jbase + jl0] = hr;
        }
        {
            // unit 1
            float4 p0 = *(const float4*)(part + (0 * 64 + b1_) * 36 + jl1 * 4);
            float4 p1 = *(const float4*)(part + (1 * 64 + b1_) * 36 + jl1 * 4);
            float4 p2 = *(const float4*)(part + (2 * 64 + b1_) * 36 + jl1 * 4);
            float4 p3 = *(const float4*)(part + (3 * 64 + b1_) * 36 + jl1 * 4);
            float gi = xv1.x + ((p0.x + p1.x) + (p2.x + p3.x));
            float gf = xv1.y + ((p0.y + p1.y) + (p2.y + p3.y));
            float gc = xv1.z + ((p0.z + p1.z) + (p2.z + p3.z));
            float go = xv1.w + ((p0.w + p1.w) + (p2.w + p3.w));
            float iv = 1.f / (1.f + __expf(-gi));
            float fv = 1.f / (1.f + __expf(-gf));
            float gv = tanhf(gc);
            float ov = 1.f / (1.f + __expf(-go));
            cc1 = fv * cc1 + iv * gv;
            float h = ov * tanhf(cc1);
            float hr = __uint_as_float(f2tf32(h));
            __stcg(hwrit + b1_ * HD + jbase + jl1, hr);
            if (STORE_OUT) out[((size_t)b1_ * T + t) * HD + jbase + jl1] = hr;
        }
        __syncthreads();

        // grid barrier: one release-add + acquire poll (CG-style)
        if (tid == 0) {
            red_release_gpu_add(bar);
            unsigned tgt = (unsigned)(t + 1) * (unsigned)NBLK;
            while (ld_acquire_gpu(bar) < tgt) { }
        }
        __syncthreads();
    }
}

// ---------------- FC head ----------------
__global__ void fc_head(const float* __restrict__ h2,     // [64][128] (buffer 0)
                        const float* __restrict__ Wfc,    // [64][128]
                        const float* __restrict__ bfc,    // [64]
                        const float* __restrict__ Wout,   // [1][64]
                        const float* __restrict__ bout,   // [1]
                        float* __restrict__ outp)         // [64]
{
    int b = threadIdx.x;  // 64 threads
    const float* hr = h2 + b * 128;
    float acc = 0.f;
    for (int uu = 0; uu < 64; uu++) {
        const float* wr = Wfc + uu * 128;
        float s0 = 0.f, s1 = 0.f, s2 = 0.f, s3 = 0.f;
#pragma unroll 8
        for (int k = 0; k < 128; k += 4) {
            s0 += hr[k]     * wr[k];
            s1 += hr[k + 1] * wr[k + 1];
            s2 += hr[k + 2] * wr[k + 2];
            s3 += hr[k + 3] * wr[k + 3];
        }
        float s = (s0 + s1) + (s2 + s3) + bfc[uu];
        acc += fmaxf(s, 0.f) * Wout[uu];
    }
    outp[b] = acc + bout[0];
}

// ---------------- launch ----------------
extern "C" void kernel_launch(void* const* d_in, const int* in_sizes, int n_in,
                              void* d_out, int out_size)
{
    const float* x    = (const float*)d_in[0];
    const float* Wih1 = (const float*)d_in[1];
    const float* Whh1 = (const float*)d_in[2];
    const float* bih1 = (const float*)d_in[3];
    const float* bhh1 = (const float*)d_in[4];
    const float* Wih2 = (const float*)d_in[5];
    const float* Whh2 = (const float*)d_in[6];
    const float* bih2 = (const float*)d_in[7];
    const float* bhh2 = (const float*)d_in[8];
    const float* Wfc1 = (const float*)d_in[9];
    const float* bfc1 = (const float*)d_in[10];
    const float* Wout = (const float*)d_in[11];
    const float* bout = (const float*)d_in[12];
    float* outp = (float*)d_out;

    float *xg1, *out1, *xg2, *w1cv, *w2cv, *h1, *h2;
    unsigned *bar1, *bar2;
    cudaGetSymbolAddress((void**)&xg1,  g_xg1);
    cudaGetSymbolAddress((void**)&out1, g_out1);
    cudaGetSymbolAddress((void**)&xg2,  g_xg2);
    cudaGetSymbolAddress((void**)&w1cv, g_w1cv);
    cudaGetSymbolAddress((void**)&w2cv, g_w2cv);
    cudaGetSymbolAddress((void**)&h1,   g_h1);
    cudaGetSymbolAddress((void**)&h2,   g_h2);
    cudaGetSymbolAddress((void**)&bar1, g_bar1);
    cudaGetSymbolAddress((void**)&bar2, g_bar2);

    const int GEMM_SMEM = 2 * 128 * 36 * 4 * 2;                       // 73728 B
    const int R1_SMEM = (64 * 260 + 32 * 260 + 4 * 64 * 36) * 4;      // 136704 B
    const int R2_SMEM = (64 * 132 + 32 * 132 + 4 * 64 * 36) * 4;      // 87552 B
    cudaFuncSetAttribute(gemm_tf32_perm,
                         cudaFuncAttributeMaxDynamicSharedMemorySize, GEMM_SMEM);
    cudaFuncSetAttribute(lstm_recur_v3<256, 32, true>,
                         cudaFuncAttributeMaxDynamicSharedMemorySize, R1_SMEM);
    cudaFuncSetAttribute(lstm_recur_v3<128, 16, false>,
                         cudaFuncAttributeMaxDynamicSharedMemorySize, R2_SMEM);

    cudaMemsetAsync(h1,   0, sizeof(float) * 2 * 64 * 256);
    cudaMemsetAsync(h2,   0, sizeof(float) * 2 * 64 * 128);
    cudaMemsetAsync(bar1, 0, sizeof(unsigned));
    cudaMemsetAsync(bar2, 0, sizeof(unsigned));

    // prep: round input-projection weights to tf32
    cvt_rna_kernel<<<(1024 * 2048 + 255) / 256, 256>>>(Wih1, w1cv, 1024 * 2048);
    cvt_rna_kernel<<<(512 * 256 + 255) / 256, 256>>>(Wih2, w2cv, 512 * 256);

    const int M = 64 * 512;

    // layer 1 input projection
    gemm_tf32_perm<<<dim3(1024 / 128, M / 128), 256, GEMM_SMEM>>>(
        x, w1cv, bih1, bhh1, xg1, M, 1024, 2048);

    // layer 1 recurrence
    lstm_recur_v3<256, 32, true><<<32, 256, R1_SMEM>>>(xg1, Whh1, h1, out1, bar1, 512);

    // layer 2 input projection
    gemm_tf32_perm<<<dim3(512 / 128, M / 128), 256, GEMM_SMEM>>>(
        out1, w2cv, bih2, bhh2, xg2, M, 512, 256);

    // layer 2 recurrence
    lstm_recur_v3<128, 16, false><<<16, 256, R2_SMEM>>>(xg2, Whh2, h2, (float*)0, bar2, 512);

    // FC head
    fc_head<<<1, 64>>>(h2, Wfc1, bfc1, Wout, bout, outp);
}

// round 5
// speedup vs baseline: 1.9317x; 1.9317x over previous
#include <cuda_runtime.h>
#include <math.h>
#include <stdint.h>

// ---------------- static device scratch (no allocation allowed) ----------------
__device__ float    g_xg1 [(size_t)32768 * 1024];   // layer1 input projection, layout [b][t][j*4+g]
__device__ float    g_out1[(size_t)32768 * 256];    // layer1 hidden outputs [b][t][j] (tf32-rounded)
__device__ float    g_xg2 [(size_t)32768 * 512];    // layer2 input projection [b][t][j*4+g]
__device__ float    g_w1cv[(size_t)1024 * 2048];    // Wih1 rounded to tf32
__device__ float    g_w2cv[(size_t)512 * 256];      // Wih2 rounded to tf32
__device__ float    g_h2f [64 * 128];               // final layer2 h

// ---------------- helpers ----------------
__device__ __forceinline__ unsigned f2tf32(float f) {
    unsigned r;
    asm("cvt.rna.tf32.f32 %0, %1;" : "=r"(r) : "f"(f));
    return r;
}

__device__ __forceinline__ void mma_tf32(float* c, const unsigned* a, const unsigned* b) {
    asm volatile(
        "mma.sync.aligned.m16n8k8.row.col.f32.tf32.tf32.f32 "
        "{%0,%1,%2,%3},{%4,%5,%6,%7},{%8,%9},{%0,%1,%2,%3};"
        : "+f"(c[0]), "+f"(c[1]), "+f"(c[2]), "+f"(c[3])
        : "r"(a[0]), "r"(a[1]), "r"(a[2]), "r"(a[3]), "r"(b[0]), "r"(b[1]));
}

__device__ __forceinline__ void cp_async16(void* smem_dst, const void* gptr) {
    unsigned s = (unsigned)__cvta_generic_to_shared(smem_dst);
    asm volatile("cp.async.cg.shared.global [%0], [%1], 16;\n" :: "r"(s), "l"(gptr));
}
#define CP_COMMIT() asm volatile("cp.async.commit_group;\n" ::: "memory")
#define CP_WAIT0()  asm volatile("cp.async.wait_group 0;\n" ::: "memory")

__device__ __forceinline__ uint32_t smem_u32(const void* p) {
    return (uint32_t)__cvta_generic_to_shared(p);
}
__device__ __forceinline__ uint32_t my_ctarank() {
    uint32_t r;
    asm("mov.u32 %0, %%cluster_ctarank;" : "=r"(r));
    return r;
}
#define CLUSTER_ARRIVE() asm volatile("barrier.cluster.arrive.aligned;" ::: "memory")
#define CLUSTER_WAIT()   asm volatile("barrier.cluster.wait.aligned;" ::: "memory")

// ---------------- prep: round weights to tf32 once ----------------
__global__ void cvt_rna_kernel(const float* __restrict__ src, float* __restrict__ dst, int n) {
    int i = blockIdx.x * 256 + threadIdx.x;
    if (i < n) dst[i] = __uint_as_float(f2tf32(src[i]));
}

// ---------------- tf32 GEMM with permuted output columns (unchanged) ----------------
__global__ void __launch_bounds__(256, 2) gemm_tf32_perm(
    const float* __restrict__ A, const float* __restrict__ W,
    const float* __restrict__ b1, const float* __restrict__ b2,
    float* __restrict__ C, int M, int N, int K)
{
    extern __shared__ unsigned sh[];
    unsigned* As = sh;                 // [2][128][36]
    unsigned* Bs = sh + 2 * 128 * 36;  // [2][128][36]

    const int tid = threadIdx.x, lane = tid & 31, warp = tid >> 5;
    const int wm = warp & 1, wn = warp >> 1;
    const int g = lane >> 2, tg = lane & 3;
    const int bn = blockIdx.x * 128, bm = blockIdx.y * 128;
    const int H = N >> 2;

    float acc[4][4][4];
#pragma unroll
    for (int a = 0; a < 4; a++)
#pragma unroll
        for (int b = 0; b < 4; b++)
#pragma unroll
            for (int c = 0; c < 4; c++) acc[a][b][c] = 0.f;

    const int NK = K >> 5;

#pragma unroll
    for (int i = 0; i < 4; i++) {
        int id = tid + i * 256, row = id >> 3, c4 = id & 7;
        cp_async16(&As[row * 36 + c4 * 4], A + (size_t)(bm + row) * K + c4 * 4);
        int np = bn + row;
        int srow = (np & 3) * H + (np >> 2);
        cp_async16(&Bs[row * 36 + c4 * 4], W + (size_t)srow * K + c4 * 4);
    }
    CP_COMMIT();

    int buf = 0;
    for (int kt = 0; kt < NK; kt++) {
        CP_WAIT0();
        __syncthreads();
        if (kt + 1 < NK) {
            int koff = (kt + 1) * 32;
            int nb = buf ^ 1;
#pragma unroll
            for (int i = 0; i < 4; i++) {
                int id = tid + i * 256, row = id >> 3, c4 = id & 7;
                cp_async16(&As[nb * 128 * 36 + row * 36 + c4 * 4],
                           A + (size_t)(bm + row) * K + koff + c4 * 4);
                int np = bn + row;
                int srow = (np & 3) * H + (np >> 2);
                cp_async16(&Bs[nb * 128 * 36 + row * 36 + c4 * 4],
                           W + (size_t)srow * K + koff + c4 * 4);
            }
        }
        CP_COMMIT();

        const unsigned* Ab = As + buf * 128 * 36;
        const unsigned* Bb = Bs + buf * 128 * 36;
#pragma unroll
        for (int ks = 0; ks < 4; ks++) {
            unsigned af[4][4], bf[4][2];
#pragma unroll
            for (int mt = 0; mt < 4; mt++) {
                int r = wm * 64 + mt * 16 + g;
                af[mt][0] = Ab[r * 36 + ks * 8 + tg];
                af[mt][1] = Ab[(r + 8) * 36 + ks * 8 + tg];
                af[mt][2] = Ab[r * 36 + ks * 8 + tg + 4];
                af[mt][3] = Ab[(r + 8) * 36 + ks * 8 + tg + 4];
            }
#pragma unroll
            for (int nt = 0; nt < 4; nt++) {
                int nl = wn * 32 + nt * 8 + g;
                bf[nt][0] = Bb[nl * 36 + ks * 8 + tg];
                bf[nt][1] = Bb[nl * 36 + ks * 8 + tg + 4];
            }
#pragma unroll
            for (int mt = 0; mt < 4; mt++)
#pragma unroll
                for (int nt = 0; nt < 4; nt++)
                    mma_tf32(acc[mt][nt], af[mt], bf[nt]);
        }
        buf ^= 1;
    }

#pragma unroll
    for (int mt = 0; mt < 4; mt++) {
        int r0 = bm + wm * 64 + mt * 16 + g;
#pragma unroll
        for (int nt = 0; nt < 4; nt++) {
            int c = bn + wn * 32 + nt * 8 + tg * 2;
            int s0 = (c & 3) * H + (c >> 2);
            int s1 = ((c + 1) & 3) * H + ((c + 1) >> 2);
            float bb0 = b1[s0] + b2[s0];
            float bb1 = b1[s1] + b2[s1];
            C[(size_t)r0 * N + c]           = acc[mt][nt][0] + bb0;
            C[(size_t)r0 * N + c + 1]       = acc[mt][nt][1] + bb1;
            C[(size_t)(r0 + 8) * N + c]     = acc[mt][nt][2] + bb0;
            C[(size_t)(r0 + 8) * N + c + 1] = acc[mt][nt][3] + bb1;
        }
    }
}

// ---------------- cluster-based LSTM recurrence (no grid barrier) ----------------
// Grid: 8 batch-groups x cluster of 8 CTAs. Batch group bg = blockIdx/8 owns
// batches [bg*8, bg*8+8); cluster rank owns JPC hidden units (jbase=rank*JPC,
// 4*JPC gate rows). Weights pre-loaded into registers (constant over t).
// Per step: C[4*JPC rows, 8 batches] = W * h^T via m16n8k8; h (all HD units for
// the 8 batches) double-buffered in SMEM; new h slice broadcast to all 8 peer
// CTAs via DSMEM; one cluster.sync per step.
// NT threads = 8*JPC (one updater thread per (batch, unit)); warps = 4*JPC/16
// m-tiles, one per warp.
template <int HD, int JPC, int NT, bool STORE_OUT>
__global__ void __launch_bounds__(256, 1) __cluster_dims__(8, 1, 1)
lstm_recur_cl(const float* __restrict__ xg,    // [b][t][j*4+g]
              const float* __restrict__ Whh,   // [4*HD][HD]
              float* __restrict__ out,         // [b][t][HD] (layer1) or null
              float* __restrict__ hfin,        // [64][HD] final h (layer2) or null
              int T)
{
    constexpr int KS  = HD / 8;        // mma k-steps
    constexpr int HDP = HD + 4;        // padded h row stride (conflict-free B frags)
    constexpr int RP  = 4 * JPC + 4;   // padded partial row stride (float4-aligned)

    extern __shared__ unsigned smem_u[];
    unsigned* hs = smem_u;                       // [2][8][HDP] tf32 h
    float* part  = (float*)(hs + 2 * 8 * HDP);   // [8][RP]

    const int tid = threadIdx.x, lane = tid & 31, warp = tid >> 5;
    const int g = lane >> 2, tg = lane & 3;
    const uint32_t rank = my_ctarank();
    const int bg = blockIdx.x >> 3;
    const int jbase = (int)rank * JPC;
    const int bglob0 = bg * 8;

    // ---- preload weight fragments into registers (once) ----
    // warp owns m-tile = local rows [warp*16, warp*16+16); local row r -> gate
    // g'=r&3, unit j=jbase+(r>>2) -> source row g'*HD + jbase + (r>>2)
    unsigned areg[KS][4];
    {
        int lr0 = warp * 16 + g, lr1 = lr0 + 8;
        const float* w0 = Whh + (size_t)((lr0 & 3) * HD + jbase + (lr0 >> 2)) * HD;
        const float* w1 = Whh + (size_t)((lr1 & 3) * HD + jbase + (lr1 >> 2)) * HD;
#pragma unroll
        for (int ks = 0; ks < KS; ks++) {
            areg[ks][0] = f2tf32(w0[ks * 8 + tg]);
            areg[ks][1] = f2tf32(w1[ks * 8 + tg]);
            areg[ks][2] = f2tf32(w0[ks * 8 + tg + 4]);
            areg[ks][3] = f2tf32(w1[ks * 8 + tg + 4]);
        }
    }

    // zero both h buffers
    for (int i = tid; i < 2 * 8 * HDP; i += NT) hs[i] = 0u;
    __syncthreads();
    CLUSTER_ARRIVE();
    CLUSTER_WAIT();

    // updater mapping: one (batch, unit) per thread
    const int b  = tid / JPC;
    const int jl = tid % JPC;
    const float* xgp = xg + ((size_t)(bglob0 + b) * T) * (4 * HD) + (jbase + jl) * 4;
    const uint32_t hs_base = smem_u32(hs);
    float cc = 0.f;

    for (int t = 0; t < T; t++) {
        // prefetch this step's xg (independent of h)
        float4 xv = *(const float4*)(xgp + (size_t)t * (4 * HD));

        // ---- mma: rows [warp*16,+16) x 8 batches, k = HD ----
        {
            float acc0[4] = {0.f, 0.f, 0.f, 0.f};
            float acc1[4] = {0.f, 0.f, 0.f, 0.f};
            const unsigned* hb = hs + (size_t)(t & 1) * 8 * HDP + g * HDP;  // batch g
#pragma unroll
            for (int ks = 0; ks < KS; ks++) {
                unsigned bf[2];
                bf[0] = hb[ks * 8 + tg];
                bf[1] = hb[ks * 8 + tg + 4];
                mma_tf32((ks & 1) ? acc1 : acc0, areg[ks], bf);
            }
            int lr = warp * 16 + g;
            part[(tg * 2 + 0) * RP + lr]     = acc0[0] + acc1[0];
            part[(tg * 2 + 1) * RP + lr]     = acc0[1] + acc1[1];
            part[(tg * 2 + 0) * RP + lr + 8] = acc0[2] + acc1[2];
            part[(tg * 2 + 1) * RP + lr + 8] = acc0[3] + acc1[3];
        }
        __syncthreads();

        // ---- update one (batch, unit) ----
        {
            float4 p = *(const float4*)(part + b * RP + jl * 4);  // gates i,f,c,o
            float gi = p.x + xv.x;
            float gf = p.y + xv.y;
            float gc = p.z + xv.z;
            float go = p.w + xv.w;
            float iv = 1.f / (1.f + __expf(-gi));
            float fv = 1.f / (1.f + __expf(-gf));
            float gv = tanhf(gc);
            float ov = 1.f / (1.f + __expf(-go));
            cc = fv * cc + iv * gv;
            float hval = ov * tanhf(cc);
            unsigned hbits = f2tf32(hval);

            // broadcast h(t)[b, jbase+jl] to all 8 cluster CTAs (same smem offset)
            uint32_t laddr = hs_base +
                (uint32_t)((((t + 1) & 1) * 8 + b) * HDP + jbase + jl) * 4u;
#pragma unroll
            for (int p8 = 0; p8 < 8; p8++) {
                uint32_t raddr;
                asm("mapa.shared::cluster.u32 %0, %1, %2;"
                    : "=r"(raddr) : "r"(laddr), "r"(p8));
                asm volatile("st.shared::cluster.b32 [%0], %1;"
                             :: "r"(raddr), "r"(hbits) : "memory");
            }
            if (STORE_OUT)
                out[((size_t)(bglob0 + b) * T + t) * HD + jbase + jl] =
                    __uint_as_float(hbits);
            if (hfin && t == T - 1)
                hfin[(size_t)(bglob0 + b) * HD + jbase + jl] = __uint_as_float(hbits);
        }

        // one cluster barrier per step (orders DSMEM writes; protects buffers)
        CLUSTER_ARRIVE();
        CLUSTER_WAIT();
    }
}

// ---------------- FC head ----------------
__global__ void fc_head(const float* __restrict__ h2,     // [64][128]
                        const float* __restrict__ Wfc,    // [64][128]
                        const float* __restrict__ bfc,    // [64]
                        const float* __restrict__ Wout,   // [1][64]
                        const float* __restrict__ bout,   // [1]
                        float* __restrict__ outp)         // [64]
{
    int b = threadIdx.x;  // 64 threads
    const float* hr = h2 + b * 128;
    float acc = 0.f;
    for (int uu = 0; uu < 64; uu++) {
        const float* wr = Wfc + uu * 128;
        float s0 = 0.f, s1 = 0.f, s2 = 0.f, s3 = 0.f;
#pragma unroll 8
        for (int k = 0; k < 128; k += 4) {
            s0 += hr[k]     * wr[k];
            s1 += hr[k + 1] * wr[k + 1];
            s2 += hr[k + 2] * wr[k + 2];
            s3 += hr[k + 3] * wr[k + 3];
        }
        float s = (s0 + s1) + (s2 + s3) + bfc[uu];
        acc += fmaxf(s, 0.f) * Wout[uu];
    }
    outp[b] = acc + bout[0];
}

// ---------------- launch ----------------
extern "C" void kernel_launch(void* const* d_in, const int* in_sizes, int n_in,
                              void* d_out, int out_size)
{
    const float* x    = (const float*)d_in[0];
    const float* Wih1 = (const float*)d_in[1];
    const float* Whh1 = (const float*)d_in[2];
    const float* bih1 = (const float*)d_in[3];
    const float* bhh1 = (const float*)d_in[4];
    const float* Wih2 = (const float*)d_in[5];
    const float* Whh2 = (const float*)d_in[6];
    const float* bih2 = (const float*)d_in[7];
    const float* bhh2 = (const float*)d_in[8];
    const float* Wfc1 = (const float*)d_in[9];
    const float* bfc1 = (const float*)d_in[10];
    const float* Wout = (const float*)d_in[11];
    const float* bout = (const float*)d_in[12];
    float* outp = (float*)d_out;

    float *xg1, *out1, *xg2, *w1cv, *w2cv, *h2f;
    cudaGetSymbolAddress((void**)&xg1,  g_xg1);
    cudaGetSymbolAddress((void**)&out1, g_out1);
    cudaGetSymbolAddress((void**)&xg2,  g_xg2);
    cudaGetSymbolAddress((void**)&w1cv, g_w1cv);
    cudaGetSymbolAddress((void**)&w2cv, g_w2cv);
    cudaGetSymbolAddress((void**)&h2f,  g_h2f);

    const int GEMM_SMEM = 2 * 128 * 36 * 4 * 2;                    // 73728 B
    const int R1_SMEM = (2 * 8 * 260) * 4 + 8 * 132 * 4;           // 20864 B
    const int R2_SMEM = (2 * 8 * 132) * 4 + 8 * 68 * 4;            // 10624 B
    cudaFuncSetAttribute(gemm_tf32_perm,
                         cudaFuncAttributeMaxDynamicSharedMemorySize, GEMM_SMEM);
    cudaFuncSetAttribute(lstm_recur_cl<256, 32, 256, true>,
                         cudaFuncAttributeMaxDynamicSharedMemorySize, 64 * 1024);
    cudaFuncSetAttribute(lstm_recur_cl<128, 16, 128, false>,
                         cudaFuncAttributeMaxDynamicSharedMemorySize, 64 * 1024);

    // prep: round input-projection weights to tf32
    cvt_rna_kernel<<<(1024 * 2048 + 255) / 256, 256>>>(Wih1, w1cv, 1024 * 2048);
    cvt_rna_kernel<<<(512 * 256 + 255) / 256, 256>>>(Wih2, w2cv, 512 * 256);

    const int M = 64 * 512;

    // layer 1 input projection
    gemm_tf32_perm<<<dim3(1024 / 128, M / 128), 256, GEMM_SMEM>>>(
        x, w1cv, bih1, bhh1, xg1, M, 1024, 2048);

    // layer 1 recurrence: 8 batch-groups x 8-CTA clusters
    lstm_recur_cl<256, 32, 256, true><<<64, 256, R1_SMEM>>>(
        xg1, Whh1, out1, (float*)0, 512);

    // layer 2 input projection
    gemm_tf32_perm<<<dim3(512 / 128, M / 128), 256, GEMM_SMEM>>>(
        out1, w2cv, bih2, bhh2, xg2, M, 512, 256);

    // layer 2 recurrence
    lstm_recur_cl<128, 16, 128, false><<<64, 128, R2_SMEM>>>(
        xg2, Whh2, (float*)0, h2f, 512);

    // FC head
    fc_head<<<1, 64>>>(h2f, Wfc1, bfc1, Wout, bout, outp);
}